// round 5
// baseline (speedup 1.0000x reference)
#include <cuda_runtime.h>
#include <stdint.h>

// out[k,l] = sum_j mitchell_mul(x[k,j], weight[l,j]) + bias[l]
// Mitchell multiply == integer add of offset float bit patterns:
//   packed(v) = (sign<<31) | max(bits(|v|) - 0x1FC00000, 0)
//   mitchell(a,b) = reinterpret_float(packed(a) + packed(b))
// (low fields < 2^30 for these inputs -> no carry into the sign bit; signs XOR)
//
// Accumulation uses FFMA with immediate 1.0 multiplier (rt_SMSP=1, vs FADD rt=2)
// to unload the fma pipe, which otherwise binds at 96 cyc/warp-k because ptxas
// alternates the integer adds between IADD3 (alu pipe) and IMAD (fma pipe).

#define NROWS 512
#define MROWS 512
#define KDIM  1024
#define SPLITS 8
#define KC (KDIM / SPLITS)   // 128 k per split
#define BK 32
#define BM 128               // x rows per CTA
#define BN 64                // w rows per CTA
#define PADM (BM + 4)
#define PADN (BN + 4)
#define TM 8
#define TN 4

__device__ float g_Part[SPLITS * NROWS * MROWS];

__device__ __forceinline__ unsigned int pack1(unsigned int b) {
    unsigned int mag = b & 0x7FFFFFFFu;
    unsigned int low = (mag > 0x1FC00000u) ? (mag - 0x1FC00000u) : 0u;
    return (b & 0x80000000u) | low;
}

__global__ __launch_bounds__(256, 2) void mitchell_mm_kernel(
    const uint4* __restrict__ xq, const uint4* __restrict__ wq, int zBase) {
    __shared__ unsigned int Xs[BK][PADM];   // [k][row]
    __shared__ unsigned int Ws[BK][PADN];

    const int tid = threadIdx.x;            // 256 threads: 16 x 16
    const int tx = tid & 15;                // col group (TN=4)
    const int ty = tid >> 4;                // row group (TM=8)
    const int z  = zBase + blockIdx.z;
    const int rowBase = blockIdx.y * BM;
    const int colBase = blockIdx.x * BN;
    const int kBase   = z * KC;
    const int K4 = KDIM / 4;

    float acc[TM][TN];
#pragma unroll
    for (int i = 0; i < TM; i++)
#pragma unroll
        for (int j = 0; j < TN; j++) acc[i][j] = 0.0f;

    // Staging: X tile 128x32 = 1024 uint4 (4/thread), W tile 64x32 = 512 uint4 (2/thread).
    const int xrow = tid >> 3;              // 0..31 (+32 per v)
    const int kq   = tid & 7;               // k-quad 0..7

    uint4 px[4], pw[2];
    auto gload = [&](int kk) {
        int gk4 = (kBase + kk) / 4 + kq;
#pragma unroll
        for (int v = 0; v < 4; v++)
            px[v] = xq[(rowBase + xrow + 32 * v) * K4 + gk4];
#pragma unroll
        for (int v = 0; v < 2; v++)
            pw[v] = wq[(colBase + xrow + 32 * v) * K4 + gk4];
    };

    auto sstore = [&]() {
#pragma unroll
        for (int v = 0; v < 4; v++) {
            int r = xrow + 32 * v;
            Xs[kq * 4 + 0][r] = pack1(px[v].x);
            Xs[kq * 4 + 1][r] = pack1(px[v].y);
            Xs[kq * 4 + 2][r] = pack1(px[v].z);
            Xs[kq * 4 + 3][r] = pack1(px[v].w);
        }
#pragma unroll
        for (int v = 0; v < 2; v++) {
            int r = xrow + 32 * v;
            Ws[kq * 4 + 0][r] = pack1(pw[v].x);
            Ws[kq * 4 + 1][r] = pack1(pw[v].y);
            Ws[kq * 4 + 2][r] = pack1(pw[v].z);
            Ws[kq * 4 + 3][r] = pack1(pw[v].w);
        }
    };

    gload(0);

    for (int s = 0; s < KC / BK; s++) {
        sstore();
        __syncthreads();
        if (s + 1 < KC / BK) gload((s + 1) * BK);

#pragma unroll 4
        for (int k = 0; k < BK; k++) {
            uint4 a0 = *reinterpret_cast<const uint4*>(&Xs[k][ty * TM]);
            uint4 a1 = *reinterpret_cast<const uint4*>(&Xs[k][ty * TM + 4]);
            uint4 b0 = *reinterpret_cast<const uint4*>(&Ws[k][tx * TN]);
            unsigned int a[TM] = {a0.x, a0.y, a0.z, a0.w, a1.x, a1.y, a1.z, a1.w};
            unsigned int b[TN] = {b0.x, b0.y, b0.z, b0.w};
#pragma unroll
            for (int i = 0; i < TM; i++)
#pragma unroll
                for (int j = 0; j < TN; j++)
                    acc[i][j] = __fmaf_rn(__uint_as_float(a[i] + b[j]), 1.0f,
                                          acc[i][j]);
        }
        __syncthreads();
    }

    float* part = g_Part + z * (NROWS * MROWS);
#pragma unroll
    for (int i = 0; i < TM; i++) {
        int r = rowBase + ty * TM + i;
        *reinterpret_cast<float4*>(&part[r * MROWS + colBase + tx * TN]) =
            make_float4(acc[i][0], acc[i][1], acc[i][2], acc[i][3]);
    }
}

__global__ __launch_bounds__(256) void reduce_kernel(
    const float* __restrict__ bias, float* __restrict__ out, int base4) {
    int i4 = base4 + blockIdx.x * blockDim.x + threadIdx.x;

    float4 p[SPLITS];
#pragma unroll
    for (int z = 0; z < SPLITS; z++)
        p[z] = reinterpret_cast<const float4*>(g_Part + z * NROWS * MROWS)[i4];

    float4 s = p[0];
#pragma unroll
    for (int z = 1; z < SPLITS; z++) {
        s.x += p[z].x; s.y += p[z].y; s.z += p[z].z; s.w += p[z].w;
    }
    float4 bv = reinterpret_cast<const float4*>(bias)[i4 & (MROWS / 4 - 1)];
    s.x += bv.x; s.y += bv.y; s.z += bv.z; s.w += bv.w;
    reinterpret_cast<float4*>(out)[i4] = s;
}

extern "C" void kernel_launch(void* const* d_in, const int* in_sizes, int n_in,
                              void* d_out, int out_size) {
    const float* x    = (const float*)d_in[0];
    const float* w    = (const float*)d_in[1];
    const float* bias = (const float*)d_in[2];
    float* out = (float*)d_out;

    // Period-4 launch pattern [mmA, mmB, redA, redB]: ncu's "-s 5 -c 1"
    // lands on launch #6 == mmB, giving a profile of the mainloop.
    dim3 grid(MROWS / BN, NROWS / BM, SPLITS / 2);   // (8,4,4) = 128 CTAs each
    mitchell_mm_kernel<<<grid, 256>>>((const uint4*)x, (const uint4*)w, 0);
    mitchell_mm_kernel<<<grid, 256>>>((const uint4*)x, (const uint4*)w, SPLITS / 2);

    const int half4 = NROWS * MROWS / 4 / 2;         // 32768 float4s per half
    reduce_kernel<<<half4 / 256, 256>>>(bias, out, 0);
    reduce_kernel<<<half4 / 256, 256>>>(bias, out, half4);
}

// round 6
// speedup vs baseline: 1.1261x; 1.1261x over previous
#include <cuda_runtime.h>
#include <stdint.h>

// out[k,l] = sum_j mitchell_mul(x[k,j], weight[l,j]) + bias[l]
// Mitchell multiply == integer add of offset float bit patterns:
//   packed(v) = (sign<<31) | max(bits(|v|) - 0x1FC00000, 0)
//   mitchell(a,b) = reinterpret_float(packed(a) + packed(b))
// (low fields < 2^30 for these inputs -> no carry into the sign bit; signs XOR)
//
// Accumulate via forced FFMA-immediate (fma.rn.f32 acc, v, 1.0, acc in asm so
// the x*1.0 cannot be simplified to FADD): FFMA-imm has rt_SMSP=1 vs FADD's 2,
// unloading the fma pipe which also carries half the integer adds as IMAD.

#define NROWS 512
#define MROWS 512
#define KDIM  1024
#define SPLITS 8
#define KC (KDIM / SPLITS)   // 128 k per split
#define BK 32
#define BM 128               // x rows per CTA
#define BN 64                // w rows per CTA
#define PADM (BM + 4)
#define PADN (BN + 4)
#define TM 8
#define TN 4

__device__ float g_Part[SPLITS * NROWS * MROWS];

__device__ __forceinline__ unsigned int pack1(unsigned int b) {
    unsigned int mag = b & 0x7FFFFFFFu;
    unsigned int low = (mag > 0x1FC00000u) ? (mag - 0x1FC00000u) : 0u;
    return (b & 0x80000000u) | low;
}

__global__ __launch_bounds__(256, 2) void mitchell_mm_kernel(
    const uint4* __restrict__ xq, const uint4* __restrict__ wq) {
    __shared__ unsigned int Xs[BK][PADM];   // [k][row]
    __shared__ unsigned int Ws[BK][PADN];

    const int tid = threadIdx.x;            // 256 threads: 16 x 16
    const int tx = tid & 15;                // col group (TN=4)
    const int ty = tid >> 4;                // row group (TM=8)
    const int rowBase = blockIdx.y * BM;
    const int colBase = blockIdx.x * BN;
    const int kBase   = blockIdx.z * KC;
    const int K4 = KDIM / 4;

    float acc[TM][TN];
#pragma unroll
    for (int i = 0; i < TM; i++)
#pragma unroll
        for (int j = 0; j < TN; j++) acc[i][j] = 0.0f;

    // Staging: X tile 128x32 = 1024 uint4 (4/thread), W tile 64x32 = 512 uint4 (2/thread).
    const int xrow = tid >> 3;              // 0..31 (+32 per v)
    const int kq   = tid & 7;               // k-quad 0..7

    uint4 px[4], pw[2];
    auto gload = [&](int kk) {
        int gk4 = (kBase + kk) / 4 + kq;
#pragma unroll
        for (int v = 0; v < 4; v++)
            px[v] = xq[(rowBase + xrow + 32 * v) * K4 + gk4];
#pragma unroll
        for (int v = 0; v < 2; v++)
            pw[v] = wq[(colBase + xrow + 32 * v) * K4 + gk4];
    };

    auto sstore = [&]() {
#pragma unroll
        for (int v = 0; v < 4; v++) {
            int r = xrow + 32 * v;
            Xs[kq * 4 + 0][r] = pack1(px[v].x);
            Xs[kq * 4 + 1][r] = pack1(px[v].y);
            Xs[kq * 4 + 2][r] = pack1(px[v].z);
            Xs[kq * 4 + 3][r] = pack1(px[v].w);
        }
#pragma unroll
        for (int v = 0; v < 2; v++) {
            int r = xrow + 32 * v;
            Ws[kq * 4 + 0][r] = pack1(pw[v].x);
            Ws[kq * 4 + 1][r] = pack1(pw[v].y);
            Ws[kq * 4 + 2][r] = pack1(pw[v].z);
            Ws[kq * 4 + 3][r] = pack1(pw[v].w);
        }
    };

    gload(0);

    for (int s = 0; s < KC / BK; s++) {
        sstore();
        __syncthreads();
        if (s + 1 < KC / BK) gload((s + 1) * BK);

#pragma unroll 4
        for (int k = 0; k < BK; k++) {
            uint4 a0 = *reinterpret_cast<const uint4*>(&Xs[k][ty * TM]);
            uint4 a1 = *reinterpret_cast<const uint4*>(&Xs[k][ty * TM + 4]);
            uint4 b0 = *reinterpret_cast<const uint4*>(&Ws[k][tx * TN]);
            unsigned int a[TM] = {a0.x, a0.y, a0.z, a0.w, a1.x, a1.y, a1.z, a1.w};
            unsigned int b[TN] = {b0.x, b0.y, b0.z, b0.w};
#pragma unroll
            for (int i = 0; i < TM; i++) {
#pragma unroll
                for (int j = 0; j < TN; j++) {
                    float v = __uint_as_float(a[i] + b[j]);
                    asm("fma.rn.f32 %0, %1, 0f3F800000, %0;"
                        : "+f"(acc[i][j]) : "f"(v));
                }
            }
        }
        __syncthreads();
    }

    float* part = g_Part + blockIdx.z * (NROWS * MROWS);
#pragma unroll
    for (int i = 0; i < TM; i++) {
        int r = rowBase + ty * TM + i;
        *reinterpret_cast<float4*>(&part[r * MROWS + colBase + tx * TN]) =
            make_float4(acc[i][0], acc[i][1], acc[i][2], acc[i][3]);
    }
}

// 256 CTAs x 256 threads: one float4 column per thread, 8 batched split loads.
__global__ __launch_bounds__(256) void reduce_kernel(
    const float* __restrict__ bias, float* __restrict__ out) {
    int i4 = blockIdx.x * blockDim.x + threadIdx.x;   // 0..65535 float4s

    float4 p[SPLITS];
#pragma unroll
    for (int z = 0; z < SPLITS; z++)
        p[z] = reinterpret_cast<const float4*>(g_Part + z * NROWS * MROWS)[i4];

    float4 s = p[0];
#pragma unroll
    for (int z = 1; z < SPLITS; z++) {
        s.x += p[z].x; s.y += p[z].y; s.z += p[z].z; s.w += p[z].w;
    }
    float4 bv = reinterpret_cast<const float4*>(bias)[i4 & (MROWS / 4 - 1)];
    s.x += bv.x; s.y += bv.y; s.z += bv.z; s.w += bv.w;
    reinterpret_cast<float4*>(out)[i4] = s;
}

extern "C" void kernel_launch(void* const* d_in, const int* in_sizes, int n_in,
                              void* d_out, int out_size) {
    const float* x    = (const float*)d_in[0];
    const float* w    = (const float*)d_in[1];
    const float* bias = (const float*)d_in[2];
    float* out = (float*)d_out;

    dim3 grid(MROWS / BN, NROWS / BM, SPLITS);   // (8,4,8) = 256 CTAs, 2/SM
    mitchell_mm_kernel<<<grid, 256>>>((const uint4*)x, (const uint4*)w);

    reduce_kernel<<<NROWS * MROWS / 4 / 256, 256>>>(bias, out);
}

// round 8
// speedup vs baseline: 1.1779x; 1.0460x over previous
#include <cuda_runtime.h>
#include <stdint.h>

// out[k,l] = sum_j mitchell_mul(x[k,j], weight[l,j]) + bias[l]
// Mitchell multiply == integer add of offset float bit patterns:
//   packed(v) = (sign<<31) | max(bits(|v|) - 0x1FC00000, 0)
//   mitchell(a,b) = reinterpret_float(packed(a) + packed(b))
// (low fields < 2^30 for these inputs -> no carry into the sign bit; signs XOR)
//
// R8: R6's latency-hiding design with BK=16 so the double-buffered smem
// (25.6 KB) fits the 48 KB static limit that killed R7.

#define NROWS 512
#define MROWS 512
#define KDIM  1024
#define SPLITS 8
#define KC (KDIM / SPLITS)   // 128 k per split
#define BK 16
#define BM 128               // x rows per CTA
#define BN 64                // w rows per CTA
#define PADM (BM + 4)
#define PADN (BN + 4)
#define TM 8
#define TN 4
#define NSTAGE (KC / BK)     // 8

__device__ float g_Part[SPLITS * NROWS * MROWS];

__device__ __forceinline__ unsigned int pack1(unsigned int b) {
    unsigned int mag = b & 0x7FFFFFFFu;
    unsigned int low = (mag > 0x1FC00000u) ? (mag - 0x1FC00000u) : 0u;
    return (b & 0x80000000u) | low;
}

__global__ __launch_bounds__(256, 2) void mitchell_mm_kernel(
    const uint4* __restrict__ xq, const uint4* __restrict__ wq) {
    __shared__ unsigned int Xs[2][BK][PADM];   // double-buffered [k][row]
    __shared__ unsigned int Ws[2][BK][PADN];

    const int tid = threadIdx.x;            // 256 threads: 16 x 16
    const int tx = tid & 15;                // col group (TN=4)
    const int ty = tid >> 4;                // row group (TM=8)
    const int rowBase = blockIdx.y * BM;
    const int colBase = blockIdx.x * BN;
    const int kBase   = blockIdx.z * KC;
    const int K4 = KDIM / 4;

    float acc[TM][TN];
#pragma unroll
    for (int i = 0; i < TM; i++)
#pragma unroll
        for (int j = 0; j < TN; j++) acc[i][j] = 0.0f;

    // Staging (BK=16): X tile 128x16 = 512 uint4 (2/thread),
    //                  W tile  64x16 = 256 uint4 (1/thread).
    const int xrow = tid >> 2;              // 0..63 (+64 for v=1)
    const int kq   = tid & 3;               // k-quad 0..3

    uint4 px[2], pw;
    auto gload = [&](int kk) {
        int gk4 = (kBase + kk) / 4 + kq;
#pragma unroll
        for (int v = 0; v < 2; v++)
            px[v] = xq[(rowBase + xrow + 64 * v) * K4 + gk4];
        pw = wq[(colBase + xrow) * K4 + gk4];
    };

    auto sstore = [&](int b) {
#pragma unroll
        for (int v = 0; v < 2; v++) {
            int r = xrow + 64 * v;
            Xs[b][kq * 4 + 0][r] = pack1(px[v].x);
            Xs[b][kq * 4 + 1][r] = pack1(px[v].y);
            Xs[b][kq * 4 + 2][r] = pack1(px[v].z);
            Xs[b][kq * 4 + 3][r] = pack1(px[v].w);
        }
        Ws[b][kq * 4 + 0][xrow] = pack1(pw.x);
        Ws[b][kq * 4 + 1][xrow] = pack1(pw.y);
        Ws[b][kq * 4 + 2][xrow] = pack1(pw.z);
        Ws[b][kq * 4 + 3][xrow] = pack1(pw.w);
    };

    gload(0);
    sstore(0);
    __syncthreads();

#pragma unroll 1
    for (int s = 0; s < NSTAGE; s++) {
        const int buf = s & 1;
        if (s + 1 < NSTAGE) gload((s + 1) * BK);   // LDG early, covered by compute

        // 2-deep register pipeline over k: load k+1 before computing k.
        unsigned int ap[2][TM], bp[2][TN];
        {
            uint4 a0 = *reinterpret_cast<const uint4*>(&Xs[buf][0][ty * TM]);
            uint4 a1 = *reinterpret_cast<const uint4*>(&Xs[buf][0][ty * TM + 4]);
            uint4 b0 = *reinterpret_cast<const uint4*>(&Ws[buf][0][tx * TN]);
            ap[0][0] = a0.x; ap[0][1] = a0.y; ap[0][2] = a0.z; ap[0][3] = a0.w;
            ap[0][4] = a1.x; ap[0][5] = a1.y; ap[0][6] = a1.z; ap[0][7] = a1.w;
            bp[0][0] = b0.x; bp[0][1] = b0.y; bp[0][2] = b0.z; bp[0][3] = b0.w;
        }
#pragma unroll
        for (int k = 0; k < BK; k++) {
            const int cur = k & 1, nxt = cur ^ 1;
            if (k + 1 < BK) {
                uint4 a0 = *reinterpret_cast<const uint4*>(&Xs[buf][k + 1][ty * TM]);
                uint4 a1 = *reinterpret_cast<const uint4*>(&Xs[buf][k + 1][ty * TM + 4]);
                uint4 b0 = *reinterpret_cast<const uint4*>(&Ws[buf][k + 1][tx * TN]);
                ap[nxt][0] = a0.x; ap[nxt][1] = a0.y; ap[nxt][2] = a0.z; ap[nxt][3] = a0.w;
                ap[nxt][4] = a1.x; ap[nxt][5] = a1.y; ap[nxt][6] = a1.z; ap[nxt][7] = a1.w;
                bp[nxt][0] = b0.x; bp[nxt][1] = b0.y; bp[nxt][2] = b0.z; bp[nxt][3] = b0.w;
            }
#pragma unroll
            for (int i = 0; i < TM; i++)
#pragma unroll
                for (int j = 0; j < TN; j++)
                    acc[i][j] += __uint_as_float(ap[cur][i] + bp[cur][j]);
        }

        if (s + 1 < NSTAGE) sstore(buf ^ 1);   // fill other buffer (bar'd last stage)
        __syncthreads();
    }

    float* part = g_Part + blockIdx.z * (NROWS * MROWS);
#pragma unroll
    for (int i = 0; i < TM; i++) {
        int r = rowBase + ty * TM + i;
        *reinterpret_cast<float4*>(&part[r * MROWS + colBase + tx * TN]) =
            make_float4(acc[i][0], acc[i][1], acc[i][2], acc[i][3]);
    }
}

// 256 CTAs x 256 threads: one float4 column per thread, 8 batched split loads.
__global__ __launch_bounds__(256) void reduce_kernel(
    const float* __restrict__ bias, float* __restrict__ out) {
    int i4 = blockIdx.x * blockDim.x + threadIdx.x;   // 0..65535 float4s

    float4 p[SPLITS];
#pragma unroll
    for (int z = 0; z < SPLITS; z++)
        p[z] = reinterpret_cast<const float4*>(g_Part + z * NROWS * MROWS)[i4];

    float4 s = p[0];
#pragma unroll
    for (int z = 1; z < SPLITS; z++) {
        s.x += p[z].x; s.y += p[z].y; s.z += p[z].z; s.w += p[z].w;
    }
    float4 bv = reinterpret_cast<const float4*>(bias)[i4 & (MROWS / 4 - 1)];
    s.x += bv.x; s.y += bv.y; s.z += bv.z; s.w += bv.w;
    reinterpret_cast<float4*>(out)[i4] = s;
}

extern "C" void kernel_launch(void* const* d_in, const int* in_sizes, int n_in,
                              void* d_out, int out_size) {
    const float* x    = (const float*)d_in[0];
    const float* w    = (const float*)d_in[1];
    const float* bias = (const float*)d_in[2];
    float* out = (float*)d_out;

    dim3 grid(MROWS / BN, NROWS / BM, SPLITS);   // (8,4,8) = 256 CTAs, 2/SM
    mitchell_mm_kernel<<<grid, 256>>>((const uint4*)x, (const uint4*)w);

    reduce_kernel<<<NROWS * MROWS / 4 / 256, 256>>>(bias, out);
}